// round 1
// baseline (speedup 1.0000x reference)
#include <cuda_runtime.h>

#define Bsz  2
#define Tlen 512
#define Dm   256
#define Mrows (Bsz*Tlen)

// Scratch (allocation-free rule: __device__ globals)
__device__ float g_k[Mrows*Dm];
__device__ float g_v[Mrows*Dm];
__device__ float g_r[Mrows*Dm];
__device__ float g_wkv[Mrows*Dm];

#define BM 64
#define BN 64
#define BK 32

// ---------------------------------------------------------------------------
// Kernel 1: fused time-mix + GEMM for k, v, r.  C[m,n] = sum_d A_z[m,d]*W_z[n,d]
// A_z[m,d] = x[m,d]*mix_z[d] + xprev[m,d]*(1-mix_z[d]);  xprev = shift by one t.
// ---------------------------------------------------------------------------
__global__ void kvr_gemm(const float* __restrict__ x, const float* __restrict__ last_x,
                         const float* __restrict__ mk, const float* __restrict__ mv,
                         const float* __restrict__ mr,
                         const float* __restrict__ Wk, const float* __restrict__ Wv,
                         const float* __restrict__ Wr)
{
    __shared__ float As[BK][BM+4];
    __shared__ float Bs[BK][BN+4];
    const int tx = threadIdx.x, ty = threadIdx.y;
    const int tid = ty*16 + tx;
    const int m0 = blockIdx.x * BM;
    const int n0 = blockIdx.y * BN;
    const int z  = blockIdx.z;

    const float* mixp = (z==0) ? mk  : (z==1) ? mv  : mr;
    const float* Wp   = (z==0) ? Wk  : (z==1) ? Wv  : Wr;
    float*       outp = (z==0) ? g_k : (z==1) ? g_v : g_r;

    float acc[4][4];
    #pragma unroll
    for (int i=0;i<4;i++)
        #pragma unroll
        for (int j=0;j<4;j++) acc[i][j]=0.f;

    const int jj = tid & 31;   // k within tile
    const int r0 = tid >> 5;   // 0..7

    for (int k0 = 0; k0 < Dm; k0 += BK) {
        #pragma unroll
        for (int r = 0; r < 8; r++) {           // A tile: 64 (m) x 32 (k), mixed on the fly
            int i  = r*8 + r0;
            int m  = m0 + i;
            int kk = k0 + jj;
            int t  = m & (Tlen-1);
            float xc = x[m*Dm + kk];
            float xp = (t==0) ? last_x[(m>>9)*Dm + kk] : x[(m-1)*Dm + kk];
            float mx = mixp[kk];
            As[jj][i] = xc*mx + xp*(1.f-mx);
        }
        #pragma unroll
        for (int r = 0; r < 8; r++) {           // B tile: W[n0+n][k0+jj]
            int n = r*8 + r0;
            Bs[jj][n] = Wp[(n0+n)*Dm + k0 + jj];
        }
        __syncthreads();
        #pragma unroll
        for (int kk=0; kk<BK; kk++){
            float4 a = *(const float4*)&As[kk][ty*4];
            float4 b = *(const float4*)&Bs[kk][tx*4];
            float av[4] = {a.x,a.y,a.z,a.w};
            float bv[4] = {b.x,b.y,b.z,b.w};
            #pragma unroll
            for (int i=0;i<4;i++)
                #pragma unroll
                for (int j=0;j<4;j++) acc[i][j] += av[i]*bv[j];
        }
        __syncthreads();
    }
    #pragma unroll
    for (int i=0;i<4;i++){
        int m = m0 + ty*4 + i;
        #pragma unroll
        for (int j=0;j<4;j++)
            outp[m*Dm + n0 + tx*4 + j] = acc[i][j];
    }
}

// ---------------------------------------------------------------------------
// Kernel 2: per-channel WKV scan (linear recurrence), one thread per (b,d).
// Also emits the three state outputs (last_x, last_num, last_den).
// ---------------------------------------------------------------------------
__global__ void wkv_scan(const float* __restrict__ x,
                         const float* __restrict__ last_num,
                         const float* __restrict__ last_den,
                         const float* __restrict__ td,
                         const float* __restrict__ tf,
                         float* __restrict__ states)
{
    int ch = blockIdx.x * blockDim.x + threadIdx.x;  // 0..511
    int b = ch >> 8;          // / Dm
    int d = ch & (Dm-1);

    float ew = __expf(-__expf(td[d]));   // e^w, w = -exp(time_decay)
    float eu = __expf(tf[d]);            // e^u
    float num = last_num[ch];
    float den = last_den[ch];

    const float* kp = g_k   + (size_t)b*Tlen*Dm + d;
    const float* vp = g_v   + (size_t)b*Tlen*Dm + d;
    float*       wp = g_wkv + (size_t)b*Tlen*Dm + d;

    float kt = kp[0], vt = vp[0];
    #pragma unroll 4
    for (int t = 0; t < Tlen; t++) {
        float kn = 0.f, vn = 0.f;
        if (t+1 < Tlen) { kn = kp[(t+1)*Dm]; vn = vp[(t+1)*Dm]; }  // prefetch
        float ek  = __expf(kt);
        float euk = eu * ek;
        float wkv = __fdividef(num + euk*vt, den + euk);
        wp[t*Dm] = wkv;
        num = ew*num + ek*vt;
        den = ew*den + ek;
        kt = kn; vt = vn;
    }
    // state outputs: [last_x (B*Dm)][last_num (B*Dm)][last_den (B*Dm)]
    states[ch]            = x[((size_t)b*Tlen + Tlen-1)*Dm + d];
    states[Bsz*Dm + ch]   = num;
    states[2*Bsz*Dm + ch] = den;
}

// ---------------------------------------------------------------------------
// Kernel 3: out = (wkv * sigmoid(r)) @ Wo^T   (sigmoid fused into A-tile load)
// ---------------------------------------------------------------------------
__global__ void out_gemm(const float* __restrict__ Wo, float* __restrict__ out)
{
    __shared__ float As[BK][BM+4];
    __shared__ float Bs[BK][BN+4];
    const int tx = threadIdx.x, ty = threadIdx.y;
    const int tid = ty*16 + tx;
    const int m0 = blockIdx.x * BM;
    const int n0 = blockIdx.y * BN;

    float acc[4][4];
    #pragma unroll
    for (int i=0;i<4;i++)
        #pragma unroll
        for (int j=0;j<4;j++) acc[i][j]=0.f;

    const int jj = tid & 31;
    const int r0 = tid >> 5;

    for (int k0 = 0; k0 < Dm; k0 += BK) {
        #pragma unroll
        for (int r = 0; r < 8; r++) {
            int i  = r*8 + r0;
            int m  = m0 + i;
            int kk = k0 + jj;
            float wv = g_wkv[m*Dm + kk];
            float rr = g_r  [m*Dm + kk];
            float sr = __fdividef(1.f, 1.f + __expf(-rr));
            As[jj][i] = wv * sr;
        }
        #pragma unroll
        for (int r = 0; r < 8; r++) {
            int n = r*8 + r0;
            Bs[jj][n] = Wo[(n0+n)*Dm + k0 + jj];
        }
        __syncthreads();
        #pragma unroll
        for (int kk=0; kk<BK; kk++){
            float4 a = *(const float4*)&As[kk][ty*4];
            float4 b = *(const float4*)&Bs[kk][tx*4];
            float av[4] = {a.x,a.y,a.z,a.w};
            float bv[4] = {b.x,b.y,b.z,b.w};
            #pragma unroll
            for (int i=0;i<4;i++)
                #pragma unroll
                for (int j=0;j<4;j++) acc[i][j] += av[i]*bv[j];
        }
        __syncthreads();
    }
    #pragma unroll
    for (int i=0;i<4;i++){
        int m = m0 + ty*4 + i;
        #pragma unroll
        for (int j=0;j<4;j++)
            out[m*Dm + n0 + tx*4 + j] = acc[i][j];
    }
}

// ---------------------------------------------------------------------------
extern "C" void kernel_launch(void* const* d_in, const int* in_sizes, int n_in,
                              void* d_out, int out_size)
{
    const float* x        = (const float*)d_in[0];
    const float* last_x   = (const float*)d_in[1];
    const float* last_num = (const float*)d_in[2];
    const float* last_den = (const float*)d_in[3];
    const float* td       = (const float*)d_in[4];
    const float* tf       = (const float*)d_in[5];
    const float* mk       = (const float*)d_in[6];
    const float* mv       = (const float*)d_in[7];
    const float* mr       = (const float*)d_in[8];
    const float* Wk       = (const float*)d_in[9];
    const float* Wv       = (const float*)d_in[10];
    const float* Wr       = (const float*)d_in[11];
    const float* Wo       = (const float*)d_in[12];
    float* out = (float*)d_out;

    dim3 blk(16,16);
    kvr_gemm<<<dim3(Mrows/BM, Dm/BN, 3), blk>>>(x, last_x, mk, mv, mr, Wk, Wv, Wr);
    wkv_scan<<<8, 64>>>(x, last_num, last_den, td, tf, out + (size_t)Mrows*Dm);
    out_gemm<<<dim3(Mrows/BM, Dm/BN), blk>>>(Wo, out);
}

// round 3
// speedup vs baseline: 2.0385x; 2.0385x over previous
#include <cuda_runtime.h>

#define Bsz  2
#define Tlen 512
#define Dm   256
#define Mrows (Bsz*Tlen)

// Scratch (allocation-free rule: __device__ globals)
__device__ float g_k[Mrows*Dm];
__device__ float g_v[Mrows*Dm];
__device__ float g_r[Mrows*Dm];
__device__ float g_wkv[Mrows*Dm];

#define BM 64
#define BN 64
#define BK 32

// ---------------------------------------------------------------------------
// Kernel 1: fused time-mix + GEMM for k, v, r.  C[m,n] = sum_d A_z[m,d]*W_z[n,d]
// ---------------------------------------------------------------------------
__global__ void kvr_gemm(const float* __restrict__ x, const float* __restrict__ last_x,
                         const float* __restrict__ mk, const float* __restrict__ mv,
                         const float* __restrict__ mr,
                         const float* __restrict__ Wk, const float* __restrict__ Wv,
                         const float* __restrict__ Wr)
{
    __shared__ float As[BK][BM+4];
    __shared__ float Bs[BK][BN+4];
    const int tx = threadIdx.x, ty = threadIdx.y;
    const int tid = ty*16 + tx;
    const int m0 = blockIdx.x * BM;
    const int n0 = blockIdx.y * BN;
    const int z  = blockIdx.z;

    const float* mixp = (z==0) ? mk  : (z==1) ? mv  : mr;
    const float* Wp   = (z==0) ? Wk  : (z==1) ? Wv  : Wr;
    float*       outp = (z==0) ? g_k : (z==1) ? g_v : g_r;

    float acc[4][4];
    #pragma unroll
    for (int i=0;i<4;i++)
        #pragma unroll
        for (int j=0;j<4;j++) acc[i][j]=0.f;

    const int jj = tid & 31;   // k within tile
    const int r0 = tid >> 5;   // 0..7

    for (int k0 = 0; k0 < Dm; k0 += BK) {
        #pragma unroll
        for (int r = 0; r < 8; r++) {           // A tile: 64 (m) x 32 (k), mixed on the fly
            int i  = r*8 + r0;
            int m  = m0 + i;
            int kk = k0 + jj;
            int t  = m & (Tlen-1);
            float xc = x[m*Dm + kk];
            float xp = (t==0) ? last_x[(m>>9)*Dm + kk] : x[(m-1)*Dm + kk];
            float mx = mixp[kk];
            As[jj][i] = xc*mx + xp*(1.f-mx);
        }
        #pragma unroll
        for (int r = 0; r < 8; r++) {           // B tile: W[n0+n][k0+jj]
            int n = r*8 + r0;
            Bs[jj][n] = Wp[(n0+n)*Dm + k0 + jj];
        }
        __syncthreads();
        #pragma unroll
        for (int kk=0; kk<BK; kk++){
            float4 a = *(const float4*)&As[kk][ty*4];
            float4 b = *(const float4*)&Bs[kk][tx*4];
            float av[4] = {a.x,a.y,a.z,a.w};
            float bv[4] = {b.x,b.y,b.z,b.w};
            #pragma unroll
            for (int i=0;i<4;i++)
                #pragma unroll
                for (int j=0;j<4;j++) acc[i][j] += av[i]*bv[j];
        }
        __syncthreads();
    }
    #pragma unroll
    for (int i=0;i<4;i++){
        int m = m0 + ty*4 + i;
        #pragma unroll
        for (int j=0;j<4;j++)
            outp[m*Dm + n0 + tx*4 + j] = acc[i][j];
    }
}

// ---------------------------------------------------------------------------
// Kernel 2: per-channel WKV scan, one thread per (b,d), batch-8 prefetch.
// Serial chain is only the 4-cyc FMA on num/den; loads exposed once per 8 steps.
// ---------------------------------------------------------------------------
#define PF 8
__global__ void wkv_scan(const float* __restrict__ x,
                         const float* __restrict__ last_num,
                         const float* __restrict__ last_den,
                         const float* __restrict__ td,
                         const float* __restrict__ tf,
                         float* __restrict__ states)
{
    int ch = blockIdx.x * blockDim.x + threadIdx.x;  // 0..511
    int b = ch >> 8;          // / Dm
    int d = ch & (Dm-1);

    float ew = __expf(-__expf(td[d]));   // e^w, w = -exp(time_decay)
    float eu = __expf(tf[d]);            // e^u
    float num = last_num[ch];
    float den = last_den[ch];

    const float* kp = g_k   + (size_t)b*Tlen*Dm + d;
    const float* vp = g_v   + (size_t)b*Tlen*Dm + d;
    float*       wp = g_wkv + (size_t)b*Tlen*Dm + d;

    float ka[PF], va[PF];
    #pragma unroll
    for (int i=0;i<PF;i++){ ka[i]=kp[i*Dm]; va[i]=vp[i*Dm]; }

    for (int t0 = 0; t0 < Tlen; t0 += PF) {
        float kn[PF], vn[PF];
        if (t0 + PF < Tlen) {
            #pragma unroll
            for (int i=0;i<PF;i++){
                kn[i] = kp[(t0+PF+i)*Dm];
                vn[i] = vp[(t0+PF+i)*Dm];
            }
        } else {
            #pragma unroll
            for (int i=0;i<PF;i++){ kn[i]=0.f; vn[i]=0.f; }
        }
        #pragma unroll
        for (int i=0;i<PF;i++){
            float ek  = __expf(ka[i]);
            float euk = eu * ek;
            float wkv = __fdividef(num + euk*va[i], den + euk);
            wp[(t0+i)*Dm] = wkv;
            num = ew*num + ek*va[i];
            den = ew*den + ek;
        }
        #pragma unroll
        for (int i=0;i<PF;i++){ ka[i]=kn[i]; va[i]=vn[i]; }
    }
    // state outputs: [last_x (B*Dm)][last_num (B*Dm)][last_den (B*Dm)]
    states[ch]            = x[((size_t)b*Tlen + Tlen-1)*Dm + d];
    states[Bsz*Dm + ch]   = num;
    states[2*Bsz*Dm + ch] = den;
}

// ---------------------------------------------------------------------------
// Kernel 3: out = (wkv * sigmoid(r)) @ Wo^T   (sigmoid fused into A-tile load)
// ---------------------------------------------------------------------------
__global__ void out_gemm(const float* __restrict__ Wo, float* __restrict__ out)
{
    __shared__ float As[BK][BM+4];
    __shared__ float Bs[BK][BN+4];
    const int tx = threadIdx.x, ty = threadIdx.y;
    const int tid = ty*16 + tx;
    const int m0 = blockIdx.x * BM;
    const int n0 = blockIdx.y * BN;

    float acc[4][4];
    #pragma unroll
    for (int i=0;i<4;i++)
        #pragma unroll
        for (int j=0;j<4;j++) acc[i][j]=0.f;

    const int jj = tid & 31;
    const int r0 = tid >> 5;

    for (int k0 = 0; k0 < Dm; k0 += BK) {
        #pragma unroll
        for (int r = 0; r < 8; r++) {
            int i  = r*8 + r0;
            int m  = m0 + i;
            int kk = k0 + jj;
            float wv = g_wkv[m*Dm + kk];
            float rr = g_r  [m*Dm + kk];
            float sr = __fdividef(1.f, 1.f + __expf(-rr));
            As[jj][i] = wv * sr;
        }
        #pragma unroll
        for (int r = 0; r < 8; r++) {
            int n = r*8 + r0;
            Bs[jj][n] = Wo[(n0+n)*Dm + k0 + jj];
        }
        __syncthreads();
        #pragma unroll
        for (int kk=0; kk<BK; kk++){
            float4 a = *(const float4*)&As[kk][ty*4];
            float4 b = *(const float4*)&Bs[kk][tx*4];
            float av[4] = {a.x,a.y,a.z,a.w};
            float bv[4] = {b.x,b.y,b.z,b.w};
            #pragma unroll
            for (int i=0;i<4;i++)
                #pragma unroll
                for (int j=0;j<4;j++) acc[i][j] += av[i]*bv[j];
        }
        __syncthreads();
    }
    #pragma unroll
    for (int i=0;i<4;i++){
        int m = m0 + ty*4 + i;
        #pragma unroll
        for (int j=0;j<4;j++)
            out[m*Dm + n0 + tx*4 + j] = acc[i][j];
    }
}

// ---------------------------------------------------------------------------
extern "C" void kernel_launch(void* const* d_in, const int* in_sizes, int n_in,
                              void* d_out, int out_size)
{
    const float* x        = (const float*)d_in[0];
    const float* last_x   = (const float*)d_in[1];
    const float* last_num = (const float*)d_in[2];
    const float* last_den = (const float*)d_in[3];
    const float* td       = (const float*)d_in[4];
    const float* tf       = (const float*)d_in[5];
    const float* mk       = (const float*)d_in[6];
    const float* mv       = (const float*)d_in[7];
    const float* mr       = (const float*)d_in[8];
    const float* Wk       = (const float*)d_in[9];
    const float* Wv       = (const float*)d_in[10];
    const float* Wr       = (const float*)d_in[11];
    const float* Wo       = (const float*)d_in[12];
    float* out = (float*)d_out;

    dim3 blk(16,16);
    kvr_gemm<<<dim3(Mrows/BM, Dm/BN, 3), blk>>>(x, last_x, mk, mv, mr, Wk, Wv, Wr);
    wkv_scan<<<16, 32>>>(x, last_num, last_den, td, tf, out + (size_t)Mrows*Dm);
    out_gemm<<<dim3(Mrows/BM, Dm/BN), blk>>>(Wo, out);
}

// round 4
// speedup vs baseline: 2.4752x; 1.2142x over previous
#include <cuda_runtime.h>

#define Bsz  2
#define Tlen 512
#define Dm   256
#define Mrows (Bsz*Tlen)
#define NCH  (Bsz*Dm)        // 512 channels

#define NC 8                 // chunks per channel
#define LC (Tlen/NC)         // 64 steps per chunk

// Scratch (allocation-free rule: __device__ globals)
__device__ float g_k  [Mrows*Dm];
__device__ float g_v  [Mrows*Dm];
__device__ float g_r  [Mrows*Dm];
__device__ float g_wkv[Mrows*Dm];
__device__ float g_ek [Mrows*Dm];
__device__ float g_ekv[Mrows*Dm];
__device__ float g_cnum[NCH*NC];
__device__ float g_cden[NCH*NC];
__device__ float g_snum[NCH*NC];
__device__ float g_sden[NCH*NC];

#define BM 64
#define BN 64
#define BK 32

// ---------------------------------------------------------------------------
// Kernel 1: fused time-mix + GEMM for k, v, r (double-buffered).
// C[m,n] = sum_d A_z[m,d] * W_z[n,d];  A_z = xp + mix_z*(x - xp), xp = shift(x)
// ---------------------------------------------------------------------------
__global__ void __launch_bounds__(256) kvr_gemm(
    const float* __restrict__ x, const float* __restrict__ last_x,
    const float* __restrict__ mk, const float* __restrict__ mv,
    const float* __restrict__ mr,
    const float* __restrict__ Wk, const float* __restrict__ Wv,
    const float* __restrict__ Wr)
{
    __shared__ float As[BK][BM+4];
    __shared__ float Bs[BK][BN+4];
    const int tx = threadIdx.x, ty = threadIdx.y;
    const int tid = ty*16 + tx;
    const int m0 = blockIdx.x * BM;
    const int n0 = blockIdx.y * BN;
    const int z  = blockIdx.z;

    const float* mixp = (z==0) ? mk  : (z==1) ? mv  : mr;
    const float* Wp   = (z==0) ? Wk  : (z==1) ? Wv  : Wr;
    float*       outp = (z==0) ? g_k : (z==1) ? g_v : g_r;

    float acc[4][4];
    #pragma unroll
    for (int i=0;i<4;i++)
        #pragma unroll
        for (int j=0;j<4;j++) acc[i][j]=0.f;

    const int jj = tid & 31;   // k within tile
    const int r0 = tid >> 5;   // 0..7

    float a_reg[8], b_reg[8];

    // prologue: stage k-tile 0
    {
        const int k0 = 0;
        #pragma unroll
        for (int r = 0; r < 8; r++) {
            int i  = r*8 + r0;
            int m  = m0 + i;
            int kk = k0 + jj;
            int t  = m & (Tlen-1);
            float xc = x[m*Dm + kk];
            float xp = (t==0) ? last_x[(m>>9)*Dm + kk] : x[(m-1)*Dm + kk];
            a_reg[r] = fmaf(xc - xp, mixp[kk], xp);
        }
        #pragma unroll
        for (int r = 0; r < 8; r++) {
            int n = r*8 + r0;
            b_reg[r] = Wp[(n0+n)*Dm + k0 + jj];
        }
    }

    for (int k0 = 0; k0 < Dm; k0 += BK) {
        #pragma unroll
        for (int r = 0; r < 8; r++) As[jj][r*8+r0] = a_reg[r];
        #pragma unroll
        for (int r = 0; r < 8; r++) Bs[jj][r*8+r0] = b_reg[r];
        __syncthreads();

        if (k0 + BK < Dm) {      // stage next tile while computing this one
            const int kn0 = k0 + BK;
            #pragma unroll
            for (int r = 0; r < 8; r++) {
                int i  = r*8 + r0;
                int m  = m0 + i;
                int kk = kn0 + jj;
                int t  = m & (Tlen-1);
                float xc = x[m*Dm + kk];
                float xp = (t==0) ? last_x[(m>>9)*Dm + kk] : x[(m-1)*Dm + kk];
                a_reg[r] = fmaf(xc - xp, mixp[kk], xp);
            }
            #pragma unroll
            for (int r = 0; r < 8; r++) {
                int n = r*8 + r0;
                b_reg[r] = Wp[(n0+n)*Dm + kn0 + jj];
            }
        }

        #pragma unroll
        for (int kk=0; kk<BK; kk++){
            float4 a = *(const float4*)&As[kk][ty*4];
            float4 b = *(const float4*)&Bs[kk][tx*4];
            float av[4] = {a.x,a.y,a.z,a.w};
            float bv[4] = {b.x,b.y,b.z,b.w};
            #pragma unroll
            for (int i=0;i<4;i++)
                #pragma unroll
                for (int j=0;j<4;j++) acc[i][j] += av[i]*bv[j];
        }
        __syncthreads();
    }
    #pragma unroll
    for (int i=0;i<4;i++){
        int m = m0 + ty*4 + i;
        *(float4*)&outp[m*Dm + n0 + tx*4] =
            make_float4(acc[i][0], acc[i][1], acc[i][2], acc[i][3]);
    }
}

// ---------------------------------------------------------------------------
// Scan pass 1: per (channel, chunk) — compute e^k, e^k*v (cached to scratch)
// and chunk-local reduction (cnum, cden) over LC=64 steps.
// ---------------------------------------------------------------------------
#define PF 8
__global__ void scan_p1(const float* __restrict__ td)
{
    int gid = blockIdx.x * blockDim.x + threadIdx.x;  // 0..4095
    int ch = gid & (NCH-1);
    int c  = gid >> 9;              // NCH = 512
    int b  = ch >> 8;
    int d  = ch & (Dm-1);

    float ew = __expf(-__expf(td[d]));
    const size_t base = (size_t)b*Tlen*Dm + (size_t)c*LC*Dm + d;
    const float* kp = g_k + base;
    const float* vp = g_v + base;
    float* ekp  = g_ek  + base;
    float* ekvp = g_ekv + base;

    float num = 0.f, den = 0.f;
    float ka[PF], va[PF];
    #pragma unroll
    for (int i=0;i<PF;i++){ ka[i]=kp[i*Dm]; va[i]=vp[i*Dm]; }

    for (int t0 = 0; t0 < LC; t0 += PF) {
        float kn[PF], vn[PF];
        if (t0 + PF < LC) {
            #pragma unroll
            for (int i=0;i<PF;i++){ kn[i]=kp[(t0+PF+i)*Dm]; vn[i]=vp[(t0+PF+i)*Dm]; }
        }
        #pragma unroll
        for (int i=0;i<PF;i++){
            float ek  = __expf(ka[i]);
            float ekv = ek * va[i];
            ekp [(t0+i)*Dm] = ek;
            ekvp[(t0+i)*Dm] = ekv;
            num = fmaf(ew, num, ekv);
            den = fmaf(ew, den, ek);
        }
        #pragma unroll
        for (int i=0;i<PF;i++){ ka[i]=kn[i]; va[i]=vn[i]; }
    }
    g_cnum[c*NCH + ch] = num;
    g_cden[c*NCH + ch] = den;
}

// ---------------------------------------------------------------------------
// Scan combine: per channel, 8-step prefix over chunk aggregates with ew^LC.
// Also emits the three state outputs.
// ---------------------------------------------------------------------------
__global__ void scan_combine(const float* __restrict__ x,
                             const float* __restrict__ last_num,
                             const float* __restrict__ last_den,
                             const float* __restrict__ td,
                             float* __restrict__ states)
{
    int ch = blockIdx.x * blockDim.x + threadIdx.x;  // 0..511
    int b = ch >> 8;
    int d = ch & (Dm-1);

    float ew = __expf(-__expf(td[d]));
    float e2 = ew*ew, e4 = e2*e2, e8 = e4*e4, e16 = e8*e8, e32 = e16*e16;
    float ewL = e32*e32;   // ew^64

    float num = last_num[ch];
    float den = last_den[ch];
    #pragma unroll
    for (int c = 0; c < NC; c++) {
        g_snum[c*NCH + ch] = num;
        g_sden[c*NCH + ch] = den;
        num = fmaf(ewL, num, g_cnum[c*NCH + ch]);
        den = fmaf(ewL, den, g_cden[c*NCH + ch]);
    }
    states[ch]         = x[((size_t)b*Tlen + Tlen-1)*Dm + d];
    states[NCH + ch]   = num;
    states[2*NCH + ch] = den;
}

// ---------------------------------------------------------------------------
// Scan pass 2: per (channel, chunk) — replay 64 steps from the chunk start
// state, reading cached e^k / e^k*v. Emits wkv. No exp on this path.
// ---------------------------------------------------------------------------
__global__ void scan_p2(const float* __restrict__ td,
                        const float* __restrict__ tf)
{
    int gid = blockIdx.x * blockDim.x + threadIdx.x;
    int ch = gid & (NCH-1);
    int c  = gid >> 9;
    int b  = ch >> 8;
    int d  = ch & (Dm-1);

    float ew = __expf(-__expf(td[d]));
    float eu = __expf(tf[d]);
    float num = g_snum[c*NCH + ch];
    float den = g_sden[c*NCH + ch];

    const size_t base = (size_t)b*Tlen*Dm + (size_t)c*LC*Dm + d;
    const float* ekp  = g_ek  + base;
    const float* ekvp = g_ekv + base;
    float* wp = g_wkv + base;

    float ea[PF], va[PF];
    #pragma unroll
    for (int i=0;i<PF;i++){ ea[i]=ekp[i*Dm]; va[i]=ekvp[i*Dm]; }

    for (int t0 = 0; t0 < LC; t0 += PF) {
        float en[PF], vn[PF];
        if (t0 + PF < LC) {
            #pragma unroll
            for (int i=0;i<PF;i++){ en[i]=ekp[(t0+PF+i)*Dm]; vn[i]=ekvp[(t0+PF+i)*Dm]; }
        }
        #pragma unroll
        for (int i=0;i<PF;i++){
            float ek  = ea[i];
            float ekv = va[i];
            float wkv = __fdividef(fmaf(eu, ekv, num), fmaf(eu, ek, den));
            wp[(t0+i)*Dm] = wkv;
            num = fmaf(ew, num, ekv);
            den = fmaf(ew, den, ek);
        }
        #pragma unroll
        for (int i=0;i<PF;i++){ ea[i]=en[i]; va[i]=vn[i]; }
    }
}

// ---------------------------------------------------------------------------
// Kernel 3: out = (wkv * sigmoid(r)) @ Wo^T  (double-buffered)
// ---------------------------------------------------------------------------
__global__ void __launch_bounds__(256) out_gemm(const float* __restrict__ Wo,
                                                float* __restrict__ out)
{
    __shared__ float As[BK][BM+4];
    __shared__ float Bs[BK][BN+4];
    const int tx = threadIdx.x, ty = threadIdx.y;
    const int tid = ty*16 + tx;
    const int m0 = blockIdx.x * BM;
    const int n0 = blockIdx.y * BN;

    float acc[4][4];
    #pragma unroll
    for (int i=0;i<4;i++)
        #pragma unroll
        for (int j=0;j<4;j++) acc[i][j]=0.f;

    const int jj = tid & 31;
    const int r0 = tid >> 5;

    float a_reg[8], b_reg[8];
    {
        const int k0 = 0;
        #pragma unroll
        for (int r = 0; r < 8; r++) {
            int i  = r*8 + r0;
            int m  = m0 + i;
            int kk = k0 + jj;
            float wv = g_wkv[m*Dm + kk];
            float rr = g_r  [m*Dm + kk];
            a_reg[r] = wv * __fdividef(1.f, 1.f + __expf(-rr));
        }
        #pragma unroll
        for (int r = 0; r < 8; r++) {
            int n = r*8 + r0;
            b_reg[r] = Wo[(n0+n)*Dm + k0 + jj];
        }
    }

    for (int k0 = 0; k0 < Dm; k0 += BK) {
        #pragma unroll
        for (int r = 0; r < 8; r++) As[jj][r*8+r0] = a_reg[r];
        #pragma unroll
        for (int r = 0; r < 8; r++) Bs[jj][r*8+r0] = b_reg[r];
        __syncthreads();

        if (k0 + BK < Dm) {
            const int kn0 = k0 + BK;
            #pragma unroll
            for (int r = 0; r < 8; r++) {
                int i  = r*8 + r0;
                int m  = m0 + i;
                int kk = kn0 + jj;
                float wv = g_wkv[m*Dm + kk];
                float rr = g_r  [m*Dm + kk];
                a_reg[r] = wv * __fdividef(1.f, 1.f + __expf(-rr));
            }
            #pragma unroll
            for (int r = 0; r < 8; r++) {
                int n = r*8 + r0;
                b_reg[r] = Wo[(n0+n)*Dm + kn0 + jj];
            }
        }

        #pragma unroll
        for (int kk=0; kk<BK; kk++){
            float4 a = *(const float4*)&As[kk][ty*4];
            float4 b = *(const float4*)&Bs[kk][tx*4];
            float av[4] = {a.x,a.y,a.z,a.w};
            float bv[4] = {b.x,b.y,b.z,b.w};
            #pragma unroll
            for (int i=0;i<4;i++)
                #pragma unroll
                for (int j=0;j<4;j++) acc[i][j] += av[i]*bv[j];
        }
        __syncthreads();
    }
    #pragma unroll
    for (int i=0;i<4;i++){
        int m = m0 + ty*4 + i;
        *(float4*)&out[m*Dm + n0 + tx*4] =
            make_float4(acc[i][0], acc[i][1], acc[i][2], acc[i][3]);
    }
}

// ---------------------------------------------------------------------------
extern "C" void kernel_launch(void* const* d_in, const int* in_sizes, int n_in,
                              void* d_out, int out_size)
{
    const float* x        = (const float*)d_in[0];
    const float* last_num = (const float*)d_in[2];
    const float* last_den = (const float*)d_in[3];
    const float* td       = (const float*)d_in[4];
    const float* tf       = (const float*)d_in[5];
    const float* mk       = (const float*)d_in[6];
    const float* mv       = (const float*)d_in[7];
    const float* mr       = (const float*)d_in[8];
    const float* Wk       = (const float*)d_in[9];
    const float* Wv       = (const float*)d_in[10];
    const float* Wr       = (const float*)d_in[11];
    const float* Wo       = (const float*)d_in[12];
    const float* last_x   = (const float*)d_in[1];
    float* out = (float*)d_out;

    dim3 blk(16,16);
    kvr_gemm<<<dim3(Mrows/BM, Dm/BN, 3), blk>>>(x, last_x, mk, mv, mr, Wk, Wv, Wr);
    scan_p1<<<32, 128>>>(td);
    scan_combine<<<2, 256>>>(x, last_num, last_den, td, out + (size_t)Mrows*Dm);
    scan_p2<<<32, 128>>>(td, tf);
    out_gemm<<<dim3(Mrows/BM, Dm/BN), blk>>>(Wo, out);
}

// round 6
// speedup vs baseline: 2.6772x; 1.0816x over previous
#include <cuda_runtime.h>

#define Bsz  2
#define Tlen 512
#define Dm   256
#define Mrows (Bsz*Tlen)
#define NCH  (Bsz*Dm)        // 512 channels

#define NC 32                // chunks per channel
#define LC (Tlen/NC)         // 16 steps per chunk

// Scratch (allocation-free rule: __device__ globals)
__device__ float g_k  [Mrows*Dm];
__device__ float g_v  [Mrows*Dm];
__device__ float g_r  [Mrows*Dm];
__device__ float g_wkv[Mrows*Dm];
__device__ float g_cnum[NCH*NC];
__device__ float g_cden[NCH*NC];
__device__ float g_snum[NCH*NC];
__device__ float g_sden[NCH*NC];

#define BM 64
#define BN 32
#define BK 32

// ---------------------------------------------------------------------------
// Kernel 1: fused time-mix + GEMM for k, v, r (double-buffered, 128 thr).
// C[m,n] = sum_d A_z[m,d] * W_z[n,d];  A_z = xp + mix_z*(x - xp), xp = shift(x)
// block (8,16): tx -> 4 n-cols, ty -> 4 m-rows
// ---------------------------------------------------------------------------
__global__ void __launch_bounds__(128) kvr_gemm(
    const float* __restrict__ x, const float* __restrict__ last_x,
    const float* __restrict__ mk, const float* __restrict__ mv,
    const float* __restrict__ mr,
    const float* __restrict__ Wk, const float* __restrict__ Wv,
    const float* __restrict__ Wr)
{
    __shared__ float As[BK][BM+4];
    __shared__ float Bs[BK][BN+4];
    const int tx = threadIdx.x, ty = threadIdx.y;
    const int tid = ty*8 + tx;
    const int m0 = blockIdx.x * BM;
    const int n0 = blockIdx.y * BN;
    const int z  = blockIdx.z;

    const float* mixp = (z==0) ? mk  : (z==1) ? mv  : mr;
    const float* Wp   = (z==0) ? Wk  : (z==1) ? Wv  : Wr;
    float*       outp = (z==0) ? g_k : (z==1) ? g_v : g_r;

    float acc[4][4];
    #pragma unroll
    for (int i=0;i<4;i++)
        #pragma unroll
        for (int j=0;j<4;j++) acc[i][j]=0.f;

    const int jj = tid & 31;   // k within tile
    const int r0 = tid >> 5;   // 0..3

    float a_reg[16], b_reg[8];

    // prologue: stage k-tile 0
    {
        #pragma unroll
        for (int r = 0; r < 16; r++) {            // A: 64 m-rows x 32 k
            int i  = r*4 + r0;
            int m  = m0 + i;
            int kk = jj;
            int t  = m & (Tlen-1);
            float xc = x[m*Dm + kk];
            float xp = (t==0) ? last_x[(m>>9)*Dm + kk] : x[(m-1)*Dm + kk];
            a_reg[r] = fmaf(xc - xp, mixp[kk], xp);
        }
        #pragma unroll
        for (int r = 0; r < 8; r++) {             // B: 32 n-rows x 32 k
            int n = r*4 + r0;
            b_reg[r] = Wp[(n0+n)*Dm + jj];
        }
    }

    for (int k0 = 0; k0 < Dm; k0 += BK) {
        #pragma unroll
        for (int r = 0; r < 16; r++) As[jj][r*4+r0] = a_reg[r];
        #pragma unroll
        for (int r = 0; r < 8;  r++) Bs[jj][r*4+r0] = b_reg[r];
        __syncthreads();

        if (k0 + BK < Dm) {      // stage next tile while computing this one
            const int kn0 = k0 + BK;
            #pragma unroll
            for (int r = 0; r < 16; r++) {
                int i  = r*4 + r0;
                int m  = m0 + i;
                int kk = kn0 + jj;
                int t  = m & (Tlen-1);
                float xc = x[m*Dm + kk];
                float xp = (t==0) ? last_x[(m>>9)*Dm + kk] : x[(m-1)*Dm + kk];
                a_reg[r] = fmaf(xc - xp, mixp[kk], xp);
            }
            #pragma unroll
            for (int r = 0; r < 8; r++) {
                int n = r*4 + r0;
                b_reg[r] = Wp[(n0+n)*Dm + kn0 + jj];
            }
        }

        #pragma unroll
        for (int kk=0; kk<BK; kk++){
            float4 a = *(const float4*)&As[kk][ty*4];
            float4 b = *(const float4*)&Bs[kk][tx*4];
            float av[4] = {a.x,a.y,a.z,a.w};
            float bv[4] = {b.x,b.y,b.z,b.w};
            #pragma unroll
            for (int i=0;i<4;i++)
                #pragma unroll
                for (int j=0;j<4;j++) acc[i][j] += av[i]*bv[j];
        }
        __syncthreads();
    }
    #pragma unroll
    for (int i=0;i<4;i++){
        int m = m0 + ty*4 + i;
        *(float4*)&outp[m*Dm + n0 + tx*4] =
            make_float4(acc[i][0], acc[i][1], acc[i][2], acc[i][3]);
    }
}

// ---------------------------------------------------------------------------
// Scan pass 1: per (channel, chunk) — chunk-local affine reduction over LC=16.
// 16384 threads.
// ---------------------------------------------------------------------------
#define PF 8
__global__ void __launch_bounds__(128) scan_p1(const float* __restrict__ td)
{
    int gid = blockIdx.x * blockDim.x + threadIdx.x;  // 0..16383
    int ch = gid & (NCH-1);
    int c  = gid >> 9;              // 0..31
    int b  = ch >> 8;
    int d  = ch & (Dm-1);

    float ew = __expf(-__expf(td[d]));
    const size_t base = (size_t)b*Tlen*Dm + (size_t)c*LC*Dm + d;
    const float* kp = g_k + base;
    const float* vp = g_v + base;

    float num = 0.f, den = 0.f;
    float ka[PF], va[PF];
    #pragma unroll
    for (int i=0;i<PF;i++){ ka[i]=kp[i*Dm]; va[i]=vp[i*Dm]; }

    for (int t0 = 0; t0 < LC; t0 += PF) {
        float kn[PF], vn[PF];
        if (t0 + PF < LC) {
            #pragma unroll
            for (int i=0;i<PF;i++){ kn[i]=kp[(t0+PF+i)*Dm]; vn[i]=vp[(t0+PF+i)*Dm]; }
        }
        #pragma unroll
        for (int i=0;i<PF;i++){
            float ek  = __expf(ka[i]);
            num = fmaf(ew, num, ek*va[i]);
            den = fmaf(ew, den, ek);
        }
        #pragma unroll
        for (int i=0;i<PF;i++){ ka[i]=kn[i]; va[i]=vn[i]; }
    }
    g_cnum[c*NCH + ch] = num;
    g_cden[c*NCH + ch] = den;
}

// ---------------------------------------------------------------------------
// Scan combine: per channel, NC-step prefix over chunk aggregates with ew^LC.
// Also emits the three state outputs.
// ---------------------------------------------------------------------------
__global__ void scan_combine(const float* __restrict__ x,
                             const float* __restrict__ last_num,
                             const float* __restrict__ last_den,
                             const float* __restrict__ td,
                             float* __restrict__ states)
{
    int ch = blockIdx.x * blockDim.x + threadIdx.x;  // 0..511
    int b = ch >> 8;
    int d = ch & (Dm-1);

    float ew = __expf(-__expf(td[d]));
    float e2 = ew*ew, e4 = e2*e2, e8 = e4*e4;
    float ewL = e8*e8;   // ew^16 (LC=16)

    float num = last_num[ch];
    float den = last_den[ch];
    #pragma unroll
    for (int c = 0; c < NC; c++) {
        g_snum[c*NCH + ch] = num;
        g_sden[c*NCH + ch] = den;
        num = fmaf(ewL, num, g_cnum[c*NCH + ch]);
        den = fmaf(ewL, den, g_cden[c*NCH + ch]);
    }
    states[ch]         = x[((size_t)b*Tlen + Tlen-1)*Dm + d];
    states[NCH + ch]   = num;
    states[2*NCH + ch] = den;
}

// ---------------------------------------------------------------------------
// Scan pass 2: replay LC=16 steps from the chunk start state; recompute exp
// (off the serial chain). Emits wkv.
// ---------------------------------------------------------------------------
__global__ void __launch_bounds__(128) scan_p2(const float* __restrict__ td,
                                               const float* __restrict__ tf)
{
    int gid = blockIdx.x * blockDim.x + threadIdx.x;
    int ch = gid & (NCH-1);
    int c  = gid >> 9;
    int b  = ch >> 8;
    int d  = ch & (Dm-1);

    float ew = __expf(-__expf(td[d]));
    float eu = __expf(tf[d]);
    float num = g_snum[c*NCH + ch];
    float den = g_sden[c*NCH + ch];

    const size_t base = (size_t)b*Tlen*Dm + (size_t)c*LC*Dm + d;
    const float* kp = g_k + base;
    const float* vp = g_v + base;
    float* wp = g_wkv + base;

    float ka[PF], va[PF];
    #pragma unroll
    for (int i=0;i<PF;i++){ ka[i]=kp[i*Dm]; va[i]=vp[i*Dm]; }

    for (int t0 = 0; t0 < LC; t0 += PF) {
        float kn[PF], vn[PF];
        if (t0 + PF < LC) {
            #pragma unroll
            for (int i=0;i<PF;i++){ kn[i]=kp[(t0+PF+i)*Dm]; vn[i]=vp[(t0+PF+i)*Dm]; }
        }
        float ek[PF], ekv[PF];
        #pragma unroll
        for (int i=0;i<PF;i++){ ek[i] = __expf(ka[i]); ekv[i] = ek[i]*va[i]; }
        #pragma unroll
        for (int i=0;i<PF;i++){
            float wkv = __fdividef(fmaf(eu, ekv[i], num), fmaf(eu, ek[i], den));
            wp[(t0+i)*Dm] = wkv;
            num = fmaf(ew, num, ekv[i]);
            den = fmaf(ew, den, ek[i]);
        }
        #pragma unroll
        for (int i=0;i<PF;i++){ ka[i]=kn[i]; va[i]=vn[i]; }
    }
}

// ---------------------------------------------------------------------------
// Kernel 3: out = (wkv * sigmoid(r)) @ Wo^T  (double-buffered, 128 thr)
// ---------------------------------------------------------------------------
__global__ void __launch_bounds__(128) out_gemm(const float* __restrict__ Wo,
                                                float* __restrict__ out)
{
    __shared__ float As[BK][BM+4];
    __shared__ float Bs[BK][BN+4];
    const int tx = threadIdx.x, ty = threadIdx.y;
    const int tid = ty*8 + tx;
    const int m0 = blockIdx.x * BM;
    const int n0 = blockIdx.y * BN;

    float acc[4][4];
    #pragma unroll
    for (int i=0;i<4;i++)
        #pragma unroll
        for (int j=0;j<4;j++) acc[i][j]=0.f;

    const int jj = tid & 31;
    const int r0 = tid >> 5;

    float a_reg[16], b_reg[8];
    {
        #pragma unroll
        for (int r = 0; r < 16; r++) {
            int i  = r*4 + r0;
            int m  = m0 + i;
            float wv = g_wkv[m*Dm + jj];
            float rr = g_r  [m*Dm + jj];
            a_reg[r] = wv * __fdividef(1.f, 1.f + __expf(-rr));
        }
        #pragma unroll
        for (int r = 0; r < 8; r++) {
            int n = r*4 + r0;
            b_reg[r] = Wo[(n0+n)*Dm + jj];
        }
    }

    for (int k0 = 0; k0 < Dm; k0 += BK) {
        #pragma unroll
        for (int r = 0; r < 16; r++) As[jj][r*4+r0] = a_reg[r];
        #pragma unroll
        for (int r = 0; r < 8;  r++) Bs[jj][r*4+r0] = b_reg[r];
        __syncthreads();

        if (k0 + BK < Dm) {
            const int kn0 = k0 + BK;
            #pragma unroll
            for (int r = 0; r < 16; r++) {
                int i  = r*4 + r0;
                int m  = m0 + i;
                float wv = g_wkv[m*Dm + kn0 + jj];
                float rr = g_r  [m*Dm + kn0 + jj];
                a_reg[r] = wv * __fdividef(1.f, 1.f + __expf(-rr));
            }
            #pragma unroll
            for (int r = 0; r < 8; r++) {
                int n = r*4 + r0;
                b_reg[r] = Wo[(n0+n)*Dm + kn0 + jj];
            }
        }

        #pragma unroll
        for (int kk=0; kk<BK; kk++){
            float4 a = *(const float4*)&As[kk][ty*4];
            float4 b = *(const float4*)&Bs[kk][tx*4];
            float av[4] = {a.x,a.y,a.z,a.w};
            float bv[4] = {b.x,b.y,b.z,b.w};
            #pragma unroll
            for (int i=0;i<4;i++)
                #pragma unroll
                for (int j=0;j<4;j++) acc[i][j] += av[i]*bv[j];
        }
        __syncthreads();
    }
    #pragma unroll
    for (int i=0;i<4;i++){
        int m = m0 + ty*4 + i;
        *(float4*)&out[m*Dm + n0 + tx*4] =
            make_float4(acc[i][0], acc[i][1], acc[i][2], acc[i][3]);
    }
}

// ---------------------------------------------------------------------------
extern "C" void kernel_launch(void* const* d_in, const int* in_sizes, int n_in,
                              void* d_out, int out_size)
{
    const float* x        = (const float*)d_in[0];
    const float* last_x   = (const float*)d_in[1];
    const float* last_num = (const float*)d_in[2];
    const float* last_den = (const float*)d_in[3];
    const float* td       = (const float*)d_in[4];
    const float* tf       = (const float*)d_in[5];
    const float* mk       = (const float*)d_in[6];
    const float* mv       = (const float*)d_in[7];
    const float* mr       = (const float*)d_in[8];
    const float* Wk       = (const float*)d_in[9];
    const float* Wv       = (const float*)d_in[10];
    const float* Wr       = (const float*)d_in[11];
    const float* Wo       = (const float*)d_in[12];
    float* out = (float*)d_out;

    dim3 blk(8,16);
    kvr_gemm<<<dim3(Mrows/BM, Dm/BN, 3), blk>>>(x, last_x, mk, mv, mr, Wk, Wv, Wr);
    scan_p1<<<128, 128>>>(td);
    scan_combine<<<2, 256>>>(x, last_num, last_den, td, out + (size_t)Mrows*Dm);
    scan_p2<<<128, 128>>>(td, tf);
    out_gemm<<<dim3(Mrows/BM, Dm/BN), blk>>>(Wo, out);
}

// round 10
// speedup vs baseline: 4.2932x; 1.6036x over previous
#include <cuda_runtime.h>
#include <cuda_bf16.h>
#include <cstdint>

#define Bsz  2
#define Tlen 512
#define Dm   256
#define Mrows (Bsz*Tlen)
#define NCH  (Bsz*Dm)        // 512 channels

#define NC 32                // chunks per channel
#define LC (Tlen/NC)         // 16 steps per chunk

// Scratch (allocation-free rule: __device__ globals)
__device__ float g_k  [Mrows*Dm];
__device__ float g_v  [Mrows*Dm];
__device__ float g_r  [Mrows*Dm];
__device__ float g_wkv[Mrows*Dm];

// ===========================================================================
// helpers
// ===========================================================================
__device__ __forceinline__ uint32_t pack_bf16(float a, float b) {
    __nv_bfloat162 h = __floats2bfloat162_rn(a, b);
    return *reinterpret_cast<uint32_t*>(&h);
}

__device__ __forceinline__ void mma_bf16(float c[4],
                                         uint32_t a0, uint32_t a1, uint32_t a2, uint32_t a3,
                                         uint32_t b0, uint32_t b1) {
    asm volatile(
        "mma.sync.aligned.m16n8k16.row.col.f32.bf16.bf16.f32 "
        "{%0,%1,%2,%3}, {%4,%5,%6,%7}, {%8,%9}, {%0,%1,%2,%3};"
        : "+f"(c[0]), "+f"(c[1]), "+f"(c[2]), "+f"(c[3])
        : "r"(a0), "r"(a1), "r"(a2), "r"(a3), "r"(b0), "r"(b1));
}

// ===========================================================================
// GEMM via mma.sync bf16x3-split.  C[m,n] = sum_k A[m,k] * W[n,k], fp32 acc.
// Tile 64x64x32, 128 threads, 2x2 warp grid, warp tile 32x32.
// MODE 0: A = time-mixed x (kvr);  MODE 1: A = wkv * sigmoid(r) (out).
// ===========================================================================
#define BK 32

template<int MODE>
__global__ void __launch_bounds__(128) mma_gemm(
    const float* __restrict__ x, const float* __restrict__ last_x,
    const float* __restrict__ mk, const float* __restrict__ mv,
    const float* __restrict__ mr,
    const float* __restrict__ Wk, const float* __restrict__ Wv,
    const float* __restrict__ Wr,
    float* __restrict__ out_override)
{
    __shared__ uint32_t Ah[64][17], Al[64][17], Bh[64][17], Bl[64][17];

    const int tid  = threadIdx.x;
    const int wid  = tid >> 5;
    const int lane = tid & 31;
    const int g    = lane >> 2;     // 0..7
    const int t    = lane & 3;      // 0..3
    const int wm   = wid & 1;       // warp m index
    const int wn   = wid >> 1;      // warp n index
    const int m0   = blockIdx.x * 64;
    const int n0   = blockIdx.y * 64;
    const int z    = blockIdx.z;

    const float* mixp = (z==0) ? mk  : (z==1) ? mv  : mr;
    const float* Wp   = (MODE==1) ? Wk /*Wo passed via Wk slot*/ :
                        ((z==0) ? Wk : (z==1) ? Wv : Wr);
    float* outp = (MODE==1) ? out_override :
                  ((z==0) ? g_k : (z==1) ? g_v : g_r);

    float acc[2][4][4];
    #pragma unroll
    for (int mi=0;mi<2;mi++)
        #pragma unroll
        for (int ni=0;ni<4;ni++)
            #pragma unroll
            for (int q=0;q<4;q++) acc[mi][ni][q]=0.f;

    for (int k0 = 0; k0 < Dm; k0 += BK) {
        // ---- stage A hi/lo (64 rows x 16 u32) ----
        #pragma unroll
        for (int e = 0; e < 8; e++) {
            int idx = tid + e*128;            // 0..1023
            int row = idx >> 4;
            int kp  = idx & 15;
            int m   = m0 + row;
            int gk  = k0 + kp*2;
            float a0f, a1f;
            if (MODE == 0) {
                int tt = m & (Tlen-1);
                float2 xc = *(const float2*)&x[(size_t)m*Dm + gk];
                float2 xp = (tt==0) ? *(const float2*)&last_x[(m>>9)*Dm + gk]
                                    : *(const float2*)&x[(size_t)(m-1)*Dm + gk];
                float2 mx = *(const float2*)&mixp[gk];
                a0f = fmaf(xc.x - xp.x, mx.x, xp.x);
                a1f = fmaf(xc.y - xp.y, mx.y, xp.y);
            } else {
                float2 wv = *(const float2*)&g_wkv[(size_t)m*Dm + gk];
                float2 rr = *(const float2*)&g_r  [(size_t)m*Dm + gk];
                a0f = wv.x * __fdividef(1.f, 1.f + __expf(-rr.x));
                a1f = wv.y * __fdividef(1.f, 1.f + __expf(-rr.y));
            }
            float h0 = __bfloat162float(__float2bfloat16(a0f));
            float h1 = __bfloat162float(__float2bfloat16(a1f));
            Ah[row][kp] = pack_bf16(h0, h1);
            Al[row][kp] = pack_bf16(a0f - h0, a1f - h1);
        }
        // ---- stage B = W hi/lo (64 n-rows x 16 u32) ----
        #pragma unroll
        for (int e = 0; e < 8; e++) {
            int idx = tid + e*128;
            int n   = idx >> 4;
            int kp  = idx & 15;
            float2 w = *(const float2*)&Wp[(size_t)(n0+n)*Dm + k0 + kp*2];
            float h0 = __bfloat162float(__float2bfloat16(w.x));
            float h1 = __bfloat162float(__float2bfloat16(w.y));
            Bh[n][kp] = pack_bf16(h0, h1);
            Bl[n][kp] = pack_bf16(w.x - h0, w.y - h1);
        }
        __syncthreads();

        // ---- 2 k16 steps ----
        #pragma unroll
        for (int s = 0; s < 2; s++) {
            const int cb = s*8;
            uint32_t ah[2][4], al[2][4], bh[4][2], bl[4][2];
            #pragma unroll
            for (int mi = 0; mi < 2; mi++) {
                int r = wm*32 + mi*16 + g;
                ah[mi][0] = Ah[r  ][cb+t];   ah[mi][1] = Ah[r+8][cb+t];
                ah[mi][2] = Ah[r  ][cb+t+4]; ah[mi][3] = Ah[r+8][cb+t+4];
                al[mi][0] = Al[r  ][cb+t];   al[mi][1] = Al[r+8][cb+t];
                al[mi][2] = Al[r  ][cb+t+4]; al[mi][3] = Al[r+8][cb+t+4];
            }
            #pragma unroll
            for (int ni = 0; ni < 4; ni++) {
                int n = wn*32 + ni*8 + g;
                bh[ni][0] = Bh[n][cb+t]; bh[ni][1] = Bh[n][cb+t+4];
                bl[ni][0] = Bl[n][cb+t]; bl[ni][1] = Bl[n][cb+t+4];
            }
            #pragma unroll
            for (int mi = 0; mi < 2; mi++)
                #pragma unroll
                for (int ni = 0; ni < 4; ni++) {
                    mma_bf16(acc[mi][ni], ah[mi][0],ah[mi][1],ah[mi][2],ah[mi][3],
                             bh[ni][0], bh[ni][1]);
                    mma_bf16(acc[mi][ni], ah[mi][0],ah[mi][1],ah[mi][2],ah[mi][3],
                             bl[ni][0], bl[ni][1]);
                    mma_bf16(acc[mi][ni], al[mi][0],al[mi][1],al[mi][2],al[mi][3],
                             bh[ni][0], bh[ni][1]);
                }
        }
        __syncthreads();
    }

    // ---- epilogue: C[g(+8)][2t,2t+1] per fragment ----
    #pragma unroll
    for (int mi = 0; mi < 2; mi++) {
        #pragma unroll
        for (int ni = 0; ni < 4; ni++) {
            int m = m0 + wm*32 + mi*16 + g;
            int n = n0 + wn*32 + ni*8 + 2*t;
            *(float2*)&outp[(size_t)m*Dm + n] =
                make_float2(acc[mi][ni][0], acc[mi][ni][1]);
            *(float2*)&outp[(size_t)(m+8)*Dm + n] =
                make_float2(acc[mi][ni][2], acc[mi][ni][3]);
        }
    }
}

// ===========================================================================
// Fused WKV scan.  One block per 32 channels; threadIdx.y = chunk.
// p1 reduction -> smem -> in-block prefix combine -> p2 replay.
// ===========================================================================
#define PF 8
__global__ void __launch_bounds__(1024) wkv_fused(
    const float* __restrict__ x,
    const float* __restrict__ last_num,
    const float* __restrict__ last_den,
    const float* __restrict__ td,
    const float* __restrict__ tf,
    float* __restrict__ states)
{
    __shared__ float s_num[NC][33];
    __shared__ float s_den[NC][33];

    const int lane = threadIdx.x;        // channel in group (0..31)
    const int c    = threadIdx.y;        // chunk (0..31)
    const int ch   = blockIdx.x * 32 + lane;
    const int b    = ch >> 8;
    const int d    = ch & (Dm-1);

    const float ew = __expf(-__expf(td[d]));
    const size_t base = (size_t)b*Tlen*Dm + (size_t)c*LC*Dm + d;
    const float* kp = g_k + base;
    const float* vp = g_v + base;

    // ---- pass 1: chunk-local affine reduction over LC=16 ----
    float ka[PF], va[PF], kb[PF], vb[PF];
    #pragma unroll
    for (int i=0;i<PF;i++){ ka[i]=kp[i*Dm];        va[i]=vp[i*Dm]; }
    #pragma unroll
    for (int i=0;i<PF;i++){ kb[i]=kp[(PF+i)*Dm];   vb[i]=vp[(PF+i)*Dm]; }

    float num = 0.f, den = 0.f;
    float ea[PF], eb[PF];
    #pragma unroll
    for (int i=0;i<PF;i++) ea[i] = __expf(ka[i]);
    #pragma unroll
    for (int i=0;i<PF;i++) eb[i] = __expf(kb[i]);
    #pragma unroll
    for (int i=0;i<PF;i++){ num = fmaf(ew, num, ea[i]*va[i]); den = fmaf(ew, den, ea[i]); }
    #pragma unroll
    for (int i=0;i<PF;i++){ num = fmaf(ew, num, eb[i]*vb[i]); den = fmaf(ew, den, eb[i]); }

    s_num[c][lane] = num;
    s_den[c][lane] = den;
    __syncthreads();

    // ---- combine: first chunk-row does 32-step prefix per channel ----
    if (c == 0) {
        float e2 = ew*ew, e4 = e2*e2, e8 = e4*e4;
        float ewL = e8*e8;                 // ew^16
        float rn = last_num[ch];
        float rd = last_den[ch];
        #pragma unroll
        for (int cc = 0; cc < NC; cc++) {
            float tn  = s_num[cc][lane];
            float tdn = s_den[cc][lane];
            s_num[cc][lane] = rn;
            s_den[cc][lane] = rd;
            rn = fmaf(ewL, rn, tn);
            rd = fmaf(ewL, rd, tdn);
        }
        states[ch]         = x[((size_t)b*Tlen + Tlen-1)*Dm + d];
        states[NCH + ch]   = rn;
        states[2*NCH + ch] = rd;
    }
    __syncthreads();

    // ---- pass 2: replay from chunk start state ----
    num = s_num[c][lane];
    den = s_den[c][lane];
    const float eu = __expf(tf[d]);
    float* wp = g_wkv + base;

    #pragma unroll
    for (int i=0;i<PF;i++){
        float ekv = ea[i]*va[i];
        wp[i*Dm] = __fdividef(fmaf(eu, ekv, num), fmaf(eu, ea[i], den));
        num = fmaf(ew, num, ekv);
        den = fmaf(ew, den, ea[i]);
    }
    #pragma unroll
    for (int i=0;i<PF;i++){
        float ekv = eb[i]*vb[i];
        wp[(PF+i)*Dm] = __fdividef(fmaf(eu, ekv, num), fmaf(eu, eb[i], den));
        num = fmaf(ew, num, ekv);
        den = fmaf(ew, den, eb[i]);
    }
}

// ---------------------------------------------------------------------------
extern "C" void kernel_launch(void* const* d_in, const int* in_sizes, int n_in,
                              void* d_out, int out_size)
{
    const float* x        = (const float*)d_in[0];
    const float* last_x   = (const float*)d_in[1];
    const float* last_num = (const float*)d_in[2];
    const float* last_den = (const float*)d_in[3];
    const float* td       = (const float*)d_in[4];
    const float* tf       = (const float*)d_in[5];
    const float* mk       = (const float*)d_in[6];
    const float* mv       = (const float*)d_in[7];
    const float* mr       = (const float*)d_in[8];
    const float* Wk       = (const float*)d_in[9];
    const float* Wv       = (const float*)d_in[10];
    const float* Wr       = (const float*)d_in[11];
    const float* Wo       = (const float*)d_in[12];
    float* out = (float*)d_out;

    // kvr: 3 fused time-mix GEMMs
    mma_gemm<0><<<dim3(Mrows/64, Dm/64, 3), 128>>>(
        x, last_x, mk, mv, mr, Wk, Wv, Wr, nullptr);
    // fused scan (also writes the 3 state outputs)
    wkv_fused<<<NCH/32, dim3(32,32)>>>(
        x, last_num, last_den, td, tf, out + (size_t)Mrows*Dm);
    // out = (wkv * sigmoid(r)) @ Wo^T   (Wo passed via the Wk slot)
    mma_gemm<1><<<dim3(Mrows/64, Dm/64, 1), 128>>>(
        x, last_x, mk, mv, mr, Wo, Wv, Wr, out);
}